// round 8
// baseline (speedup 1.0000x reference)
#include <cuda_runtime.h>
#include <cuda_fp16.h>
#include <cstdint>
#include <cstddef>

// ---------------------------------------------------------------------------
// Problem constants
// ---------------------------------------------------------------------------
#define BB_ 4
#define TT_ 4096
#define DD_ 1024
#define MM_ (BB_ * TT_)   // 16384 rows
#define E3_ (3 * DD_)     // 3072

// ---------------------------------------------------------------------------
// Scratch (static device globals -- allocation-free rule)
// ---------------------------------------------------------------------------
__device__ float g_qkv[(size_t)MM_ * E3_];
__device__ __half g_xh[(size_t)MM_ * DD_];     // x fp16, reused as A2 fp16
__device__ __half g_wqh[(size_t)E3_ * DD_];
__device__ __half g_woh[(size_t)DD_ * DD_];
__device__ float g_invq[MM_];
__device__ float g_kv[BB_ * DD_];
__device__ int   g_mask_is_byte;

// ---------------------------------------------------------------------------
// Helpers (sm_103 baseline ISA: cp.async, ldmatrix, mma.sync)
// ---------------------------------------------------------------------------
__device__ __forceinline__ uint32_t smem_to_u32(const void* smem_ptr) {
    uint32_t addr;
    asm("{ .reg .u64 tmp; cvta.to.shared.u64 tmp, %1; cvt.u32.u64 %0, tmp; }"
        : "=r"(addr) : "l"(smem_ptr));
    return addr;
}

__device__ __forceinline__ void cp16(uint32_t smem_dst, const void* gmem_src) {
    asm volatile("cp.async.cg.shared.global [%0], [%1], 16;\n"
                 :: "r"(smem_dst), "l"(gmem_src));
}
#define CP_ASYNC_COMMIT() asm volatile("cp.async.commit_group;\n" ::: "memory")
#define CP_ASYNC_WAIT_2() asm volatile("cp.async.wait_group 2;\n" ::: "memory")
#define CP_ASYNC_WAIT_1() asm volatile("cp.async.wait_group 1;\n" ::: "memory")
#define CP_ASYNC_WAIT_0() asm volatile("cp.async.wait_group 0;\n" ::: "memory")

#define LDSM_X4(r0, r1, r2, r3, addr) \
    asm volatile("ldmatrix.sync.aligned.m8n8.x4.shared.b16 {%0,%1,%2,%3}, [%4];" \
                 : "=r"(r0), "=r"(r1), "=r"(r2), "=r"(r3) : "r"(addr))

// fp16 MMA with fp32 accumulate
#define MMA_16816_F16(c, a, b) \
    asm volatile("mma.sync.aligned.m16n8k16.row.col.f32.f16.f16.f32 " \
                 "{%0,%1,%2,%3}, {%4,%5,%6,%7}, {%8,%9}, {%0,%1,%2,%3};" \
                 : "+f"((c)[0]), "+f"((c)[1]), "+f"((c)[2]), "+f"((c)[3]) \
                 : "r"((a)[0]), "r"((a)[1]), "r"((a)[2]), "r"((a)[3]), \
                   "r"((b)[0]), "r"((b)[1]))

#define SMEM_SWIZZLE_128B(byte_offset) \
    ((byte_offset) ^ (((byte_offset) >> 3) & 0x70))

// ---------------------------------------------------------------------------
// fp16 GEMM: C[M,N] = A @ B^T + bias      (A:(M,1024) B:(N,1024) fp16 rowmaj)
// CTA tile 128(M) x 256(N), BK=64; 512 thr = 16 warps 4(M)x4(N), warp 32x64.
// Stage: [A 16KB][B 32KB] = 48KB; 4-stage cp.async ring (192KB), 3-deep
// prefetch. Per-warp ks rotation de-phases crossbar bursts vs MMA.
// ---------------------------------------------------------------------------
#define STAGES 4
#define STAGE_BYTES 49152
#define GS_TOTAL (STAGES * STAGE_BYTES)   // 196608
#define NKT 16                            // 1024 / 64
#define NTHR 512

__device__ __forceinline__ void gemm_issue_load(
    uint32_t sb, int slot, int tid, int m0, int n0, int k0,
    const __half* __restrict__ A, const __half* __restrict__ B)
{
    uint32_t base = sb + slot * STAGE_BYTES;
    #pragma unroll
    for (int i = 0; i < 2; i++) {           // A: 128 rows x 8 chunks = 1024
        int id = tid + (i << 9);
        int r  = id >> 3;
        int cc = id & 7;
        uint32_t soff = SMEM_SWIZZLE_128B((uint32_t)((r << 7) + (cc << 4)));
        cp16(base + soff, A + (size_t)(m0 + r) * DD_ + k0 + (cc << 3));
    }
    #pragma unroll
    for (int i = 0; i < 4; i++) {           // B: 256 rows x 8 chunks = 2048
        int id = tid + (i << 9);
        int r  = id >> 3;
        int cc = id & 7;
        uint32_t soff = SMEM_SWIZZLE_128B((uint32_t)((r << 7) + (cc << 4)));
        cp16(base + 16384 + soff, B + (size_t)(n0 + r) * DD_ + k0 + (cc << 3));
    }
    CP_ASYNC_COMMIT();
}

__global__ __launch_bounds__(NTHR, 1) void gemm_f16_kernel(
    const __half* __restrict__ A, const __half* __restrict__ B,
    const float* __restrict__ bias, float* __restrict__ C, int N)
{
    extern __shared__ char smem[];
    uint32_t sb = smem_to_u32(smem);
    const int tid = threadIdx.x;
    const int wid = tid >> 5;
    const int lane = tid & 31;
    const int n0 = blockIdx.x * 256;   // N fast-varying: wave shares A via L2
    const int m0 = blockIdx.y * 128;
    const int warp_m = (wid & 3) * 32;     // 4 M-groups of 32
    const int warp_n = (wid >> 2) * 64;    // 4 N-groups of 64
    const int kphase = wid & 3;            // ks rotation per warp

    // ldmatrix per-lane address components (validated R2-R7)
    const int lr = lane & 7;
    const int a_row = warp_m + lr + ((lane & 8) ? 8 : 0);
    const int a_ksel = (lane & 16) ? 16 : 0;
    const int b_row = warp_n + lr + ((lane & 16) ? 8 : 0);
    const int b_ksel = (lane & 8) ? 16 : 0;

    float acc[2][8][4];
    #pragma unroll
    for (int i = 0; i < 2; i++)
        #pragma unroll
        for (int j = 0; j < 8; j++)
            #pragma unroll
            for (int k = 0; k < 4; k++) acc[i][j][k] = 0.0f;

    // prologue: stages 0,1,2 (3-deep prefetch)
    gemm_issue_load(sb, 0, tid, m0, n0, 0,   A, B);
    gemm_issue_load(sb, 1, tid, m0, n0, 64,  A, B);
    gemm_issue_load(sb, 2, tid, m0, n0, 128, A, B);

    for (int it = 0; it < NKT; it++) {
        // ensure data(it) has landed: pending <= {it+1, it+2}
        if (it < NKT - 2)      { CP_ASYNC_WAIT_2(); }
        else if (it == NKT - 2){ CP_ASYNC_WAIT_1(); }
        else                   { CP_ASYNC_WAIT_0(); }
        __syncthreads();

        int nt = it + 3;
        if (nt < NKT)
            gemm_issue_load(sb, nt & 3, tid, m0, n0, nt << 6, A, B);

        uint32_t ab = sb + (it & 3) * STAGE_BYTES;
        uint32_t bb = ab + 16384;

        #pragma unroll
        for (int kk = 0; kk < 4; kk++) {
            int ks = (kk + kphase) & 3;
            uint32_t koff = (uint32_t)(ks << 5);
            uint32_t bfr[8][2];
            uint32_t afr[2][4];
            // B nb=0 (tiles 0,1)
            {
                int row = b_row;
                uint32_t addr = bb + (uint32_t)(row << 7)
                              + ((koff + b_ksel) ^ (uint32_t)((row & 7) << 4));
                LDSM_X4(bfr[0][0], bfr[0][1], bfr[1][0], bfr[1][1], addr);
            }
            // A fragments (2 m16 tiles)
            #pragma unroll
            for (int mf = 0; mf < 2; mf++) {
                int row = a_row + mf * 16;
                uint32_t addr = ab + (uint32_t)(row << 7)
                              + ((koff + a_ksel) ^ (uint32_t)((row & 7) << 4));
                LDSM_X4(afr[mf][0], afr[mf][1], afr[mf][2], afr[mf][3], addr);
            }
            // B nb=1 (tiles 2,3)
            {
                int row = b_row + 16;
                uint32_t addr = bb + (uint32_t)(row << 7)
                              + ((koff + b_ksel) ^ (uint32_t)((row & 7) << 4));
                LDSM_X4(bfr[2][0], bfr[2][1], bfr[3][0], bfr[3][1], addr);
            }
            // MMA on tiles 0,1 while nb=2 loads
            #pragma unroll
            for (int mf = 0; mf < 2; mf++) {
                MMA_16816_F16(acc[mf][0], afr[mf], bfr[0]);
                MMA_16816_F16(acc[mf][1], afr[mf], bfr[1]);
            }
            // B nb=2 (tiles 4,5)
            {
                int row = b_row + 32;
                uint32_t addr = bb + (uint32_t)(row << 7)
                              + ((koff + b_ksel) ^ (uint32_t)((row & 7) << 4));
                LDSM_X4(bfr[4][0], bfr[4][1], bfr[5][0], bfr[5][1], addr);
            }
            #pragma unroll
            for (int mf = 0; mf < 2; mf++) {
                MMA_16816_F16(acc[mf][2], afr[mf], bfr[2]);
                MMA_16816_F16(acc[mf][3], afr[mf], bfr[3]);
            }
            // B nb=3 (tiles 6,7)
            {
                int row = b_row + 48;
                uint32_t addr = bb + (uint32_t)(row << 7)
                              + ((koff + b_ksel) ^ (uint32_t)((row & 7) << 4));
                LDSM_X4(bfr[6][0], bfr[6][1], bfr[7][0], bfr[7][1], addr);
            }
            #pragma unroll
            for (int mf = 0; mf < 2; mf++) {
                MMA_16816_F16(acc[mf][4], afr[mf], bfr[4]);
                MMA_16816_F16(acc[mf][5], afr[mf], bfr[5]);
            }
            #pragma unroll
            for (int mf = 0; mf < 2; mf++) {
                MMA_16816_F16(acc[mf][6], afr[mf], bfr[6]);
                MMA_16816_F16(acc[mf][7], afr[mf], bfr[7]);
            }
        }
    }

    // epilogue: regs -> gmem with bias
    const int gid = lane >> 2;
    const int t4 = lane & 3;
    #pragma unroll
    for (int mf = 0; mf < 2; mf++) {
        int r0 = m0 + warp_m + mf * 16 + gid;
        #pragma unroll
        for (int nf = 0; nf < 8; nf++) {
            int c = n0 + warp_n + nf * 8 + t4 * 2;
            float2 b2 = *(const float2*)(bias + c);
            float2 v0 = make_float2(acc[mf][nf][0] + b2.x, acc[mf][nf][1] + b2.y);
            float2 v1 = make_float2(acc[mf][nf][2] + b2.x, acc[mf][nf][3] + b2.y);
            *(float2*)(C + (size_t)r0 * N + c) = v0;
            *(float2*)(C + (size_t)(r0 + 8) * N + c) = v1;
        }
    }
}

// ---------------------------------------------------------------------------
// Elementwise / reduction kernels
// ---------------------------------------------------------------------------

// fp32 -> fp16 convert, 8 elems/thread
__global__ void cvt_f16_kernel(const float* __restrict__ in,
                               __half* __restrict__ out, int n8)
{
    int idx = blockIdx.x * blockDim.x + threadIdx.x;
    if (idx >= n8) return;
    float4 a = ((const float4*)in)[idx * 2];
    float4 b = ((const float4*)in)[idx * 2 + 1];
    union { uint4 u; __half2 h[4]; } r;
    r.h[0] = __floats2half2_rn(a.x, a.y);
    r.h[1] = __floats2half2_rn(a.z, a.w);
    r.h[2] = __floats2half2_rn(b.x, b.y);
    r.h[3] = __floats2half2_rn(b.z, b.w);
    ((uint4*)out)[idx] = r.u;
}

__global__ void zero_kv_kernel(float* __restrict__ kv)
{
    int i = blockIdx.x * blockDim.x + threadIdx.x;
    if (i < BB_ * DD_) kv[i] = 0.0f;
}

__global__ void detect_mask_kernel(const unsigned char* __restrict__ m)
{
    __shared__ int any;
    if (threadIdx.x == 0) any = 0;
    __syncthreads();
    int acc = 0;
    for (int i = threadIdx.x; i < MM_; i += blockDim.x)
        if ((i & 3) != 0) acc |= m[i];
    if (acc) atomicOr(&any, 1);
    __syncthreads();
    if (threadIdx.x == 0) g_mask_is_byte = any ? 1 : 0;
}

__global__ __launch_bounds__(256) void stage2_kernel(
    const float* __restrict__ qkv, const unsigned char* __restrict__ mask,
    float* __restrict__ invq, float* __restrict__ kv)
{
    __shared__ float s_ik[32];
    int tid = threadIdx.x, lane = tid & 31, warp = tid >> 5;
    int R0 = blockIdx.x * 32;
    int b = R0 >> 12;
    int maskIsByte = g_mask_is_byte;
    const int* mask32 = (const int*)mask;

    #pragma unroll
    for (int rr = 0; rr < 4; rr++) {
        int row = R0 + warp * 4 + rr;
        const float4* base = (const float4*)(qkv + (size_t)row * E3_);
        float sq = 0.f, sk = 0.f;
        #pragma unroll
        for (int j = 0; j < 8; j++) {
            float4 q4 = base[lane + 32 * j];
            float4 k4 = base[256 + lane + 32 * j];
            sq += q4.x*q4.x + q4.y*q4.y + q4.z*q4.z + q4.w*q4.w;
            sk += k4.x*k4.x + k4.y*k4.y + k4.z*k4.z + k4.w*k4.w;
        }
        #pragma unroll
        for (int o = 16; o > 0; o >>= 1) {
            sq += __shfl_xor_sync(0xffffffffu, sq, o);
            sk += __shfl_xor_sync(0xffffffffu, sk, o);
        }
        if (lane == 0) {
            invq[row] = rsqrtf(sq);
            s_ik[warp * 4 + rr] = rsqrtf(sk);
        }
    }
    __syncthreads();

    float ax = 0.f, ay = 0.f, az = 0.f, aw = 0.f;
    for (int r = 0; r < 32; r++) {
        int row = R0 + r;
        bool msk = maskIsByte ? (mask[row] != 0) : (mask32[row] != 0);
        if (!msk) {
            float ik = s_ik[r];
            const float4* base = (const float4*)(qkv + (size_t)row * E3_);
            float4 k4 = base[256 + tid];
            float4 v4 = base[512 + tid];
            ax += k4.x * ik * v4.x;
            ay += k4.y * ik * v4.y;
            az += k4.z * ik * v4.z;
            aw += k4.w * ik * v4.w;
        }
    }
    float* kvb = kv + b * DD_ + tid * 4;
    atomicAdd(kvb + 0, ax);
    atomicAdd(kvb + 1, ay);
    atomicAdd(kvb + 2, az);
    atomicAdd(kvb + 3, aw);
}

// A2 = q * invq[row] * kv[b,:] -> fp16. One 128-thread block per row.
__global__ __launch_bounds__(128) void stage3_kernel(
    const float* __restrict__ qkv, const float* __restrict__ invq,
    const float* __restrict__ kv, __half* __restrict__ out)
{
    int tid = threadIdx.x;
    int row = blockIdx.x;
    int b = row >> 12;
    float s = invq[row];
    const float* qp = qkv + (size_t)row * E3_ + tid * 8;
    const float* kp = kv + b * DD_ + tid * 8;
    float4 q0 = *(const float4*)(qp);
    float4 q1 = *(const float4*)(qp + 4);
    float4 k0 = *(const float4*)(kp);
    float4 k1 = *(const float4*)(kp + 4);
    union { uint4 u; __half2 h[4]; } r;
    r.h[0] = __floats2half2_rn(q0.x * s * k0.x, q0.y * s * k0.y);
    r.h[1] = __floats2half2_rn(q0.z * s * k0.z, q0.w * s * k0.w);
    r.h[2] = __floats2half2_rn(q1.x * s * k1.x, q1.y * s * k1.y);
    r.h[3] = __floats2half2_rn(q1.z * s * k1.z, q1.w * s * k1.w);
    *(uint4*)(out + (size_t)row * DD_ + tid * 8) = r.u;
}

// ---------------------------------------------------------------------------
// Launch
// ---------------------------------------------------------------------------
extern "C" void kernel_launch(void* const* d_in, const int* in_sizes, int n_in,
                              void* d_out, int out_size)
{
    const float* x = (const float*)d_in[0];
    const unsigned char* mask = (const unsigned char*)d_in[1];
    const float* Wqkv = (const float*)d_in[2];
    const float* bqkv = (const float*)d_in[3];
    const float* Wout = (const float*)d_in[4];
    const float* bout = (const float*)d_in[5];
    float* out = (float*)d_out;

    float *p_qkv, *p_invq, *p_kv;
    __half *p_xh, *p_wqh, *p_woh;
    cudaGetSymbolAddress((void**)&p_qkv, g_qkv);
    cudaGetSymbolAddress((void**)&p_invq, g_invq);
    cudaGetSymbolAddress((void**)&p_kv, g_kv);
    cudaGetSymbolAddress((void**)&p_xh, g_xh);
    cudaGetSymbolAddress((void**)&p_wqh, g_wqh);
    cudaGetSymbolAddress((void**)&p_woh, g_woh);

    cudaFuncSetAttribute(gemm_f16_kernel,
                         cudaFuncAttributeMaxDynamicSharedMemorySize, GS_TOTAL);

    // Launch order keeps GEMM1 at ncu capture slot #4 (-s 5 -c 1).
    zero_kv_kernel<<<(BB_ * DD_ + 255) / 256, 256>>>(p_kv);
    cvt_f16_kernel<<<(MM_ * DD_ / 8 + 255) / 256, 256>>>(x, p_xh, MM_ * DD_ / 8);
    cvt_f16_kernel<<<(E3_ * DD_ / 8 + 255) / 256, 256>>>(Wqkv, p_wqh, E3_ * DD_ / 8);
    // 4: GEMM1: qkv = x @ W_qkv^T + b_qkv   (16384 x 3072)
    gemm_f16_kernel<<<dim3(E3_ / 256, MM_ / 128), NTHR, GS_TOTAL>>>(
        p_xh, p_wqh, bqkv, p_qkv, E3_);
    cvt_f16_kernel<<<(DD_ * DD_ / 8 + 255) / 256, 256>>>(Wout, p_woh, DD_ * DD_ / 8);
    detect_mask_kernel<<<1, 512>>>(mask);
    stage2_kernel<<<MM_ / 32, 256>>>(p_qkv, mask, p_invq, p_kv);
    // A2 fp16 overwrites x fp16 buffer
    stage3_kernel<<<MM_, 128>>>(p_qkv, p_invq, p_kv, p_xh);
    // GEMM2: out = A2 @ W_out^T + b_out   (16384 x 1024)
    gemm_f16_kernel<<<dim3(DD_ / 256, MM_ / 128), NTHR, GS_TOTAL>>>(
        p_xh, p_woh, bout, out, DD_);
}

// round 9
// speedup vs baseline: 1.1335x; 1.1335x over previous
#include <cuda_runtime.h>
#include <cuda_fp16.h>
#include <cstdint>
#include <cstddef>

// ---------------------------------------------------------------------------
// Problem constants
// ---------------------------------------------------------------------------
#define BB_ 4
#define TT_ 4096
#define DD_ 1024
#define MM_ (BB_ * TT_)   // 16384 rows
#define E3_ (3 * DD_)     // 3072

// ---------------------------------------------------------------------------
// Scratch (static device globals -- allocation-free rule)
// ---------------------------------------------------------------------------
__device__ float g_qkv[(size_t)MM_ * E3_];
__device__ __half g_xh[(size_t)MM_ * DD_];     // x fp16, reused as A2 fp16
__device__ __half g_wqh[(size_t)E3_ * DD_];
__device__ __half g_woh[(size_t)DD_ * DD_];
__device__ float g_invq[MM_];
__device__ float g_kv[BB_ * DD_];
__device__ int   g_mask_is_byte;

// ---------------------------------------------------------------------------
// Helpers (sm_103 baseline ISA: cp.async, ldmatrix, mma.sync)
// ---------------------------------------------------------------------------
__device__ __forceinline__ uint32_t smem_to_u32(const void* smem_ptr) {
    uint32_t addr;
    asm("{ .reg .u64 tmp; cvta.to.shared.u64 tmp, %1; cvt.u32.u64 %0, tmp; }"
        : "=r"(addr) : "l"(smem_ptr));
    return addr;
}

__device__ __forceinline__ void cp16(uint32_t smem_dst, const void* gmem_src) {
    asm volatile("cp.async.cg.shared.global [%0], [%1], 16;\n"
                 :: "r"(smem_dst), "l"(gmem_src));
}
#define CP_ASYNC_COMMIT() asm volatile("cp.async.commit_group;\n" ::: "memory")
#define CP_ASYNC_WAIT_1() asm volatile("cp.async.wait_group 1;\n" ::: "memory")
#define CP_ASYNC_WAIT_0() asm volatile("cp.async.wait_group 0;\n" ::: "memory")

#define LDSM_X4(r0, r1, r2, r3, addr) \
    asm volatile("ldmatrix.sync.aligned.m8n8.x4.shared.b16 {%0,%1,%2,%3}, [%4];" \
                 : "=r"(r0), "=r"(r1), "=r"(r2), "=r"(r3) : "r"(addr))

// fp16 MMA with fp32 accumulate
#define MMA_16816_F16(c, a, b) \
    asm volatile("mma.sync.aligned.m16n8k16.row.col.f32.f16.f16.f32 " \
                 "{%0,%1,%2,%3}, {%4,%5,%6,%7}, {%8,%9}, {%0,%1,%2,%3};" \
                 : "+f"((c)[0]), "+f"((c)[1]), "+f"((c)[2]), "+f"((c)[3]) \
                 : "r"((a)[0]), "r"((a)[1]), "r"((a)[2]), "r"((a)[3]), \
                   "r"((b)[0]), "r"((b)[1]))

#define SMEM_SWIZZLE_128B(byte_offset) \
    ((byte_offset) ^ (((byte_offset) >> 3) & 0x70))

// ---------------------------------------------------------------------------
// fp16 GEMM: C[M,N] = A @ B^T + bias      (A:(M,1024) B:(N,1024) fp16 rowmaj)
// CTA tile 128(M) x 128(N), BK=64; 256 thr = 8 warps 2(M)x4(N), warp 64x32.
// Stage: [A 16KB][B 16KB] = 32KB; 3-stage ring = 96KB -> 2 CTAs/SM so one
// CTA's barrier stalls are covered by the other CTA's warps.
// ---------------------------------------------------------------------------
#define STAGES 3
#define STAGE_BYTES 32768
#define GS_TOTAL (STAGES * STAGE_BYTES)   // 98304 (2 CTAs -> 192KB/SM)
#define NKT 16                            // 1024 / 64
#define NTHR 256

__device__ __forceinline__ void gemm_issue_load(
    uint32_t sb, int slot, int tid, int m0, int n0, int k0,
    const __half* __restrict__ A, const __half* __restrict__ B)
{
    uint32_t base = sb + slot * STAGE_BYTES;
    #pragma unroll
    for (int i = 0; i < 4; i++) {           // A: 128 rows x 8 chunks = 1024
        int id = tid + (i << 8);
        int r  = id >> 3;
        int cc = id & 7;
        uint32_t soff = SMEM_SWIZZLE_128B((uint32_t)((r << 7) + (cc << 4)));
        cp16(base + soff, A + (size_t)(m0 + r) * DD_ + k0 + (cc << 3));
    }
    #pragma unroll
    for (int i = 0; i < 4; i++) {           // B: 128 rows x 8 chunks = 1024
        int id = tid + (i << 8);
        int r  = id >> 3;
        int cc = id & 7;
        uint32_t soff = SMEM_SWIZZLE_128B((uint32_t)((r << 7) + (cc << 4)));
        cp16(base + 16384 + soff, B + (size_t)(n0 + r) * DD_ + k0 + (cc << 3));
    }
    CP_ASYNC_COMMIT();
}

__global__ __launch_bounds__(NTHR, 2) void gemm_f16_kernel(
    const __half* __restrict__ A, const __half* __restrict__ B,
    const float* __restrict__ bias, float* __restrict__ C, int N)
{
    extern __shared__ char smem[];
    uint32_t sb = smem_to_u32(smem);
    const int tid = threadIdx.x;
    const int wid = tid >> 5;
    const int lane = tid & 31;
    const int n0 = blockIdx.x * 128;   // N fast-varying: wave shares A via L2
    const int m0 = blockIdx.y * 128;
    const int warp_m = (wid & 1) * 64;     // 2 M-groups of 64
    const int warp_n = (wid >> 1) * 32;    // 4 N-groups of 32

    // ldmatrix per-lane address components (validated R2-R8)
    const int lr = lane & 7;
    const int a_row = warp_m + lr + ((lane & 8) ? 8 : 0);
    const int a_ksel = (lane & 16) ? 16 : 0;
    const int b_row = warp_n + lr + ((lane & 16) ? 8 : 0);
    const int b_ksel = (lane & 8) ? 16 : 0;

    float acc[4][4][4];
    #pragma unroll
    for (int i = 0; i < 4; i++)
        #pragma unroll
        for (int j = 0; j < 4; j++)
            #pragma unroll
            for (int k = 0; k < 4; k++) acc[i][j][k] = 0.0f;

    // prologue: stages 0,1
    gemm_issue_load(sb, 0, tid, m0, n0, 0,  A, B);
    gemm_issue_load(sb, 1, tid, m0, n0, 64, A, B);

    int slot = 0;
    for (int it = 0; it < NKT; it++) {
        if (it == NKT - 1) { CP_ASYNC_WAIT_0(); } else { CP_ASYNC_WAIT_1(); }
        __syncthreads();

        int nt = it + 2;
        if (nt < NKT) {
            int ns = slot + 2; if (ns >= STAGES) ns -= STAGES;
            gemm_issue_load(sb, ns, tid, m0, n0, nt << 6, A, B);
        }

        uint32_t ab = sb + slot * STAGE_BYTES;
        uint32_t bb = ab + 16384;

        #pragma unroll
        for (int ks = 0; ks < 4; ks++) {
            uint32_t koff = (uint32_t)(ks << 5);
            // B fragments: 32 columns = 2 LDSM_X4 (4 n8 tiles)
            uint32_t bfr[4][2];
            #pragma unroll
            for (int nb = 0; nb < 2; nb++) {
                int row = b_row + nb * 16;
                uint32_t addr = bb + (uint32_t)(row << 7)
                              + ((koff + b_ksel) ^ (uint32_t)((row & 7) << 4));
                LDSM_X4(bfr[2 * nb][0], bfr[2 * nb][1],
                        bfr[2 * nb + 1][0], bfr[2 * nb + 1][1], addr);
            }
            // A fragments: 64 rows = 4 LDSM_X4
            uint32_t afr[4][4];
            #pragma unroll
            for (int mf = 0; mf < 4; mf++) {
                int row = a_row + mf * 16;
                uint32_t addr = ab + (uint32_t)(row << 7)
                              + ((koff + a_ksel) ^ (uint32_t)((row & 7) << 4));
                LDSM_X4(afr[mf][0], afr[mf][1], afr[mf][2], afr[mf][3], addr);
            }
            #pragma unroll
            for (int mf = 0; mf < 4; mf++)
                #pragma unroll
                for (int nf = 0; nf < 4; nf++)
                    MMA_16816_F16(acc[mf][nf], afr[mf], bfr[nf]);
        }
        slot++; if (slot >= STAGES) slot = 0;
    }

    // epilogue: regs -> gmem with bias
    const int gid = lane >> 2;
    const int t4 = lane & 3;
    #pragma unroll
    for (int mf = 0; mf < 4; mf++) {
        int r0 = m0 + warp_m + mf * 16 + gid;
        #pragma unroll
        for (int nf = 0; nf < 4; nf++) {
            int c = n0 + warp_n + nf * 8 + t4 * 2;
            float2 b2 = *(const float2*)(bias + c);
            float2 v0 = make_float2(acc[mf][nf][0] + b2.x, acc[mf][nf][1] + b2.y);
            float2 v1 = make_float2(acc[mf][nf][2] + b2.x, acc[mf][nf][3] + b2.y);
            *(float2*)(C + (size_t)r0 * N + c) = v0;
            *(float2*)(C + (size_t)(r0 + 8) * N + c) = v1;
        }
    }
}

// ---------------------------------------------------------------------------
// Elementwise / reduction kernels
// ---------------------------------------------------------------------------

// fp32 -> fp16 convert, 8 elems/thread
__global__ void cvt_f16_kernel(const float* __restrict__ in,
                               __half* __restrict__ out, int n8)
{
    int idx = blockIdx.x * blockDim.x + threadIdx.x;
    if (idx >= n8) return;
    float4 a = ((const float4*)in)[idx * 2];
    float4 b = ((const float4*)in)[idx * 2 + 1];
    union { uint4 u; __half2 h[4]; } r;
    r.h[0] = __floats2half2_rn(a.x, a.y);
    r.h[1] = __floats2half2_rn(a.z, a.w);
    r.h[2] = __floats2half2_rn(b.x, b.y);
    r.h[3] = __floats2half2_rn(b.z, b.w);
    ((uint4*)out)[idx] = r.u;
}

__global__ void zero_kv_kernel(float* __restrict__ kv)
{
    int i = blockIdx.x * blockDim.x + threadIdx.x;
    if (i < BB_ * DD_) kv[i] = 0.0f;
}

__global__ void detect_mask_kernel(const unsigned char* __restrict__ m)
{
    __shared__ int any;
    if (threadIdx.x == 0) any = 0;
    __syncthreads();
    int acc = 0;
    for (int i = threadIdx.x; i < MM_; i += blockDim.x)
        if ((i & 3) != 0) acc |= m[i];
    if (acc) atomicOr(&any, 1);
    __syncthreads();
    if (threadIdx.x == 0) g_mask_is_byte = any ? 1 : 0;
}

__global__ __launch_bounds__(256) void stage2_kernel(
    const float* __restrict__ qkv, const unsigned char* __restrict__ mask,
    float* __restrict__ invq, float* __restrict__ kv)
{
    __shared__ float s_ik[32];
    int tid = threadIdx.x, lane = tid & 31, warp = tid >> 5;
    int R0 = blockIdx.x * 32;
    int b = R0 >> 12;
    int maskIsByte = g_mask_is_byte;
    const int* mask32 = (const int*)mask;

    #pragma unroll
    for (int rr = 0; rr < 4; rr++) {
        int row = R0 + warp * 4 + rr;
        const float4* base = (const float4*)(qkv + (size_t)row * E3_);
        float sq = 0.f, sk = 0.f;
        #pragma unroll
        for (int j = 0; j < 8; j++) {
            float4 q4 = base[lane + 32 * j];
            float4 k4 = base[256 + lane + 32 * j];
            sq += q4.x*q4.x + q4.y*q4.y + q4.z*q4.z + q4.w*q4.w;
            sk += k4.x*k4.x + k4.y*k4.y + k4.z*k4.z + k4.w*k4.w;
        }
        #pragma unroll
        for (int o = 16; o > 0; o >>= 1) {
            sq += __shfl_xor_sync(0xffffffffu, sq, o);
            sk += __shfl_xor_sync(0xffffffffu, sk, o);
        }
        if (lane == 0) {
            invq[row] = rsqrtf(sq);
            s_ik[warp * 4 + rr] = rsqrtf(sk);
        }
    }
    __syncthreads();

    float ax = 0.f, ay = 0.f, az = 0.f, aw = 0.f;
    for (int r = 0; r < 32; r++) {
        int row = R0 + r;
        bool msk = maskIsByte ? (mask[row] != 0) : (mask32[row] != 0);
        if (!msk) {
            float ik = s_ik[r];
            const float4* base = (const float4*)(qkv + (size_t)row * E3_);
            float4 k4 = base[256 + tid];
            float4 v4 = base[512 + tid];
            ax += k4.x * ik * v4.x;
            ay += k4.y * ik * v4.y;
            az += k4.z * ik * v4.z;
            aw += k4.w * ik * v4.w;
        }
    }
    float* kvb = kv + b * DD_ + tid * 4;
    atomicAdd(kvb + 0, ax);
    atomicAdd(kvb + 1, ay);
    atomicAdd(kvb + 2, az);
    atomicAdd(kvb + 3, aw);
}

// A2 = q * invq[row] * kv[b,:] -> fp16. One 128-thread block per row.
__global__ __launch_bounds__(128) void stage3_kernel(
    const float* __restrict__ qkv, const float* __restrict__ invq,
    const float* __restrict__ kv, __half* __restrict__ out)
{
    int tid = threadIdx.x;
    int row = blockIdx.x;
    int b = row >> 12;
    float s = invq[row];
    const float* qp = qkv + (size_t)row * E3_ + tid * 8;
    const float* kp = kv + b * DD_ + tid * 8;
    float4 q0 = *(const float4*)(qp);
    float4 q1 = *(const float4*)(qp + 4);
    float4 k0 = *(const float4*)(kp);
    float4 k1 = *(const float4*)(kp + 4);
    union { uint4 u; __half2 h[4]; } r;
    r.h[0] = __floats2half2_rn(q0.x * s * k0.x, q0.y * s * k0.y);
    r.h[1] = __floats2half2_rn(q0.z * s * k0.z, q0.w * s * k0.w);
    r.h[2] = __floats2half2_rn(q1.x * s * k1.x, q1.y * s * k1.y);
    r.h[3] = __floats2half2_rn(q1.z * s * k1.z, q1.w * s * k1.w);
    *(uint4*)(out + (size_t)row * DD_ + tid * 8) = r.u;
}

// ---------------------------------------------------------------------------
// Launch
// ---------------------------------------------------------------------------
extern "C" void kernel_launch(void* const* d_in, const int* in_sizes, int n_in,
                              void* d_out, int out_size)
{
    const float* x = (const float*)d_in[0];
    const unsigned char* mask = (const unsigned char*)d_in[1];
    const float* Wqkv = (const float*)d_in[2];
    const float* bqkv = (const float*)d_in[3];
    const float* Wout = (const float*)d_in[4];
    const float* bout = (const float*)d_in[5];
    float* out = (float*)d_out;

    float *p_qkv, *p_invq, *p_kv;
    __half *p_xh, *p_wqh, *p_woh;
    cudaGetSymbolAddress((void**)&p_qkv, g_qkv);
    cudaGetSymbolAddress((void**)&p_invq, g_invq);
    cudaGetSymbolAddress((void**)&p_kv, g_kv);
    cudaGetSymbolAddress((void**)&p_xh, g_xh);
    cudaGetSymbolAddress((void**)&p_wqh, g_wqh);
    cudaGetSymbolAddress((void**)&p_woh, g_woh);

    cudaFuncSetAttribute(gemm_f16_kernel,
                         cudaFuncAttributeMaxDynamicSharedMemorySize, GS_TOTAL);

    // Launch order keeps GEMM1 at ncu capture slot #4 (-s 5 -c 1).
    zero_kv_kernel<<<(BB_ * DD_ + 255) / 256, 256>>>(p_kv);
    cvt_f16_kernel<<<(MM_ * DD_ / 8 + 255) / 256, 256>>>(x, p_xh, MM_ * DD_ / 8);
    cvt_f16_kernel<<<(E3_ * DD_ / 8 + 255) / 256, 256>>>(Wqkv, p_wqh, E3_ * DD_ / 8);
    // 4: GEMM1: qkv = x @ W_qkv^T + b_qkv   (16384 x 3072)
    gemm_f16_kernel<<<dim3(E3_ / 128, MM_ / 128), NTHR, GS_TOTAL>>>(
        p_xh, p_wqh, bqkv, p_qkv, E3_);
    cvt_f16_kernel<<<(DD_ * DD_ / 8 + 255) / 256, 256>>>(Wout, p_woh, DD_ * DD_ / 8);
    detect_mask_kernel<<<1, 512>>>(mask);
    stage2_kernel<<<MM_ / 32, 256>>>(p_qkv, mask, p_invq, p_kv);
    // A2 fp16 overwrites x fp16 buffer
    stage3_kernel<<<MM_, 128>>>(p_qkv, p_invq, p_kv, p_xh);
    // GEMM2: out = A2 @ W_out^T + b_out   (16384 x 1024)
    gemm_f16_kernel<<<dim3(DD_ / 128, MM_ / 128), NTHR, GS_TOTAL>>>(
        p_xh, p_woh, bout, out, DD_);
}

// round 10
// speedup vs baseline: 1.1859x; 1.0462x over previous
#include <cuda_runtime.h>
#include <cuda_fp16.h>
#include <cstdint>
#include <cstddef>

// ---------------------------------------------------------------------------
// Problem constants
// ---------------------------------------------------------------------------
#define BB_ 4
#define TT_ 4096
#define DD_ 1024
#define MM_ (BB_ * TT_)   // 16384 rows
#define E3_ (3 * DD_)     // 3072

// ---------------------------------------------------------------------------
// Scratch (static device globals -- allocation-free rule)
// ---------------------------------------------------------------------------
__device__ float g_qkv[(size_t)MM_ * E3_];
__device__ __half g_xh[(size_t)MM_ * DD_];     // x fp16, reused as A2 fp16
__device__ __half g_wqh[(size_t)E3_ * DD_];
__device__ __half g_woh[(size_t)DD_ * DD_];
__device__ float g_invq[MM_];
__device__ float g_kv[BB_ * DD_];
__device__ int   g_mask_is_byte;

// ---------------------------------------------------------------------------
// Helpers (sm_103 baseline ISA: cp.async, ldmatrix, mma.sync)
// ---------------------------------------------------------------------------
__device__ __forceinline__ uint32_t smem_to_u32(const void* smem_ptr) {
    uint32_t addr;
    asm("{ .reg .u64 tmp; cvta.to.shared.u64 tmp, %1; cvt.u32.u64 %0, tmp; }"
        : "=r"(addr) : "l"(smem_ptr));
    return addr;
}

__device__ __forceinline__ void cp16(uint32_t smem_dst, const void* gmem_src) {
    asm volatile("cp.async.cg.shared.global [%0], [%1], 16;\n"
                 :: "r"(smem_dst), "l"(gmem_src));
}
#define CP_ASYNC_COMMIT() asm volatile("cp.async.commit_group;\n" ::: "memory")
#define CP_ASYNC_WAIT_1() asm volatile("cp.async.wait_group 1;\n" ::: "memory")
#define CP_ASYNC_WAIT_0() asm volatile("cp.async.wait_group 0;\n" ::: "memory")

#define LDSM_X4(r0, r1, r2, r3, addr) \
    asm volatile("ldmatrix.sync.aligned.m8n8.x4.shared.b16 {%0,%1,%2,%3}, [%4];" \
                 : "=r"(r0), "=r"(r1), "=r"(r2), "=r"(r3) : "r"(addr))

// fp16 MMA with fp32 accumulate
#define MMA_16816_F16(c, a, b) \
    asm volatile("mma.sync.aligned.m16n8k16.row.col.f32.f16.f16.f32 " \
                 "{%0,%1,%2,%3}, {%4,%5,%6,%7}, {%8,%9}, {%0,%1,%2,%3};" \
                 : "+f"((c)[0]), "+f"((c)[1]), "+f"((c)[2]), "+f"((c)[3]) \
                 : "r"((a)[0]), "r"((a)[1]), "r"((a)[2]), "r"((a)[3]), \
                   "r"((b)[0]), "r"((b)[1]))

#define SMEM_SWIZZLE_128B(byte_offset) \
    ((byte_offset) ^ (((byte_offset) >> 3) & 0x70))

// ---------------------------------------------------------------------------
// fp16 GEMM: C[M,N] = A @ B^T + bias      (A:(M,1024) B:(N,1024) fp16 rowmaj)
// CTA tile 128(M) x 128(N), BK=64; 128 thr = 4 warps 2(M)x2(N), warp 64x64.
// 64x64 warp tile = 16 MAC/byte of LDSM traffic -> crossbar no longer binds.
// Stage: [A 16KB][B 16KB] = 32KB; 3-stage ring = 96KB -> 2 CTAs/SM; the two
// independent CTAs cover each other's barrier/epilogue stalls.
// ---------------------------------------------------------------------------
#define STAGES 3
#define STAGE_BYTES 32768
#define GS_TOTAL (STAGES * STAGE_BYTES)   // 98304 (2 CTAs -> 192KB/SM)
#define NKT 16                            // 1024 / 64
#define NTHR 128

__device__ __forceinline__ void gemm_issue_load(
    uint32_t sb, int slot, int tid, int m0, int n0, int k0,
    const __half* __restrict__ A, const __half* __restrict__ B)
{
    uint32_t base = sb + slot * STAGE_BYTES;
    #pragma unroll
    for (int i = 0; i < 8; i++) {           // A: 128 rows x 8 chunks = 1024
        int id = tid + (i << 7);
        int r  = id >> 3;
        int cc = id & 7;
        uint32_t soff = SMEM_SWIZZLE_128B((uint32_t)((r << 7) + (cc << 4)));
        cp16(base + soff, A + (size_t)(m0 + r) * DD_ + k0 + (cc << 3));
    }
    #pragma unroll
    for (int i = 0; i < 8; i++) {           // B: 128 rows x 8 chunks = 1024
        int id = tid + (i << 7);
        int r  = id >> 3;
        int cc = id & 7;
        uint32_t soff = SMEM_SWIZZLE_128B((uint32_t)((r << 7) + (cc << 4)));
        cp16(base + 16384 + soff, B + (size_t)(n0 + r) * DD_ + k0 + (cc << 3));
    }
    CP_ASYNC_COMMIT();
}

__global__ __launch_bounds__(NTHR, 2) void gemm_f16_kernel(
    const __half* __restrict__ A, const __half* __restrict__ B,
    const float* __restrict__ bias, float* __restrict__ C, int N)
{
    extern __shared__ char smem[];
    uint32_t sb = smem_to_u32(smem);
    const int tid = threadIdx.x;
    const int wid = tid >> 5;
    const int lane = tid & 31;
    const int n0 = blockIdx.x * 128;   // N fast-varying: wave shares A via L2
    const int m0 = blockIdx.y * 128;
    const int warp_m = (wid & 1) * 64;     // 2 M-groups of 64
    const int warp_n = (wid >> 1) * 64;    // 2 N-groups of 64

    // ldmatrix per-lane address components (validated R2-R9)
    const int lr = lane & 7;
    const int a_row = warp_m + lr + ((lane & 8) ? 8 : 0);
    const int a_ksel = (lane & 16) ? 16 : 0;
    const int b_row = warp_n + lr + ((lane & 16) ? 8 : 0);
    const int b_ksel = (lane & 8) ? 16 : 0;

    float acc[4][8][4];
    #pragma unroll
    for (int i = 0; i < 4; i++)
        #pragma unroll
        for (int j = 0; j < 8; j++)
            #pragma unroll
            for (int k = 0; k < 4; k++) acc[i][j][k] = 0.0f;

    // prologue: stages 0,1
    gemm_issue_load(sb, 0, tid, m0, n0, 0,  A, B);
    gemm_issue_load(sb, 1, tid, m0, n0, 64, A, B);

    int slot = 0;
    for (int it = 0; it < NKT; it++) {
        if (it == NKT - 1) { CP_ASYNC_WAIT_0(); } else { CP_ASYNC_WAIT_1(); }
        __syncthreads();

        int nt = it + 2;
        if (nt < NKT) {
            int ns = slot + 2; if (ns >= STAGES) ns -= STAGES;
            gemm_issue_load(sb, ns, tid, m0, n0, nt << 6, A, B);
        }

        uint32_t ab = sb + slot * STAGE_BYTES;
        uint32_t bb = ab + 16384;

        #pragma unroll
        for (int ks = 0; ks < 4; ks++) {
            uint32_t koff = (uint32_t)(ks << 5);
            // B fragments: 64 columns = 4 LDSM_X4 (8 n8 tiles)
            uint32_t bfr[8][2];
            #pragma unroll
            for (int nb = 0; nb < 4; nb++) {
                int row = b_row + nb * 16;
                uint32_t addr = bb + (uint32_t)(row << 7)
                              + ((koff + b_ksel) ^ (uint32_t)((row & 7) << 4));
                LDSM_X4(bfr[2 * nb][0], bfr[2 * nb][1],
                        bfr[2 * nb + 1][0], bfr[2 * nb + 1][1], addr);
            }
            // A fragments: 64 rows = 4 LDSM_X4
            uint32_t afr[4][4];
            #pragma unroll
            for (int mf = 0; mf < 4; mf++) {
                int row = a_row + mf * 16;
                uint32_t addr = ab + (uint32_t)(row << 7)
                              + ((koff + a_ksel) ^ (uint32_t)((row & 7) << 4));
                LDSM_X4(afr[mf][0], afr[mf][1], afr[mf][2], afr[mf][3], addr);
            }
            #pragma unroll
            for (int mf = 0; mf < 4; mf++)
                #pragma unroll
                for (int nf = 0; nf < 8; nf++)
                    MMA_16816_F16(acc[mf][nf], afr[mf], bfr[nf]);
        }
        slot++; if (slot >= STAGES) slot = 0;
    }

    // epilogue: regs -> gmem with bias
    const int gid = lane >> 2;
    const int t4 = lane & 3;
    #pragma unroll
    for (int mf = 0; mf < 4; mf++) {
        int r0 = m0 + warp_m + mf * 16 + gid;
        #pragma unroll
        for (int nf = 0; nf < 8; nf++) {
            int c = n0 + warp_n + nf * 8 + t4 * 2;
            float2 b2 = *(const float2*)(bias + c);
            float2 v0 = make_float2(acc[mf][nf][0] + b2.x, acc[mf][nf][1] + b2.y);
            float2 v1 = make_float2(acc[mf][nf][2] + b2.x, acc[mf][nf][3] + b2.y);
            *(float2*)(C + (size_t)r0 * N + c) = v0;
            *(float2*)(C + (size_t)(r0 + 8) * N + c) = v1;
        }
    }
}

// ---------------------------------------------------------------------------
// Elementwise / reduction kernels
// ---------------------------------------------------------------------------

// fp32 -> fp16 convert, 8 elems/thread
__global__ void cvt_f16_kernel(const float* __restrict__ in,
                               __half* __restrict__ out, int n8)
{
    int idx = blockIdx.x * blockDim.x + threadIdx.x;
    if (idx >= n8) return;
    float4 a = ((const float4*)in)[idx * 2];
    float4 b = ((const float4*)in)[idx * 2 + 1];
    union { uint4 u; __half2 h[4]; } r;
    r.h[0] = __floats2half2_rn(a.x, a.y);
    r.h[1] = __floats2half2_rn(a.z, a.w);
    r.h[2] = __floats2half2_rn(b.x, b.y);
    r.h[3] = __floats2half2_rn(b.z, b.w);
    ((uint4*)out)[idx] = r.u;
}

__global__ void zero_kv_kernel(float* __restrict__ kv)
{
    int i = blockIdx.x * blockDim.x + threadIdx.x;
    if (i < BB_ * DD_) kv[i] = 0.0f;
}

__global__ void detect_mask_kernel(const unsigned char* __restrict__ m)
{
    __shared__ int any;
    if (threadIdx.x == 0) any = 0;
    __syncthreads();
    int acc = 0;
    for (int i = threadIdx.x; i < MM_; i += blockDim.x)
        if ((i & 3) != 0) acc |= m[i];
    if (acc) atomicOr(&any, 1);
    __syncthreads();
    if (threadIdx.x == 0) g_mask_is_byte = any ? 1 : 0;
}

__global__ __launch_bounds__(256) void stage2_kernel(
    const float* __restrict__ qkv, const unsigned char* __restrict__ mask,
    float* __restrict__ invq, float* __restrict__ kv)
{
    __shared__ float s_ik[32];
    int tid = threadIdx.x, lane = tid & 31, warp = tid >> 5;
    int R0 = blockIdx.x * 32;
    int b = R0 >> 12;
    int maskIsByte = g_mask_is_byte;
    const int* mask32 = (const int*)mask;

    #pragma unroll
    for (int rr = 0; rr < 4; rr++) {
        int row = R0 + warp * 4 + rr;
        const float4* base = (const float4*)(qkv + (size_t)row * E3_);
        float sq = 0.f, sk = 0.f;
        #pragma unroll
        for (int j = 0; j < 8; j++) {
            float4 q4 = base[lane + 32 * j];
            float4 k4 = base[256 + lane + 32 * j];
            sq += q4.x*q4.x + q4.y*q4.y + q4.z*q4.z + q4.w*q4.w;
            sk += k4.x*k4.x + k4.y*k4.y + k4.z*k4.z + k4.w*k4.w;
        }
        #pragma unroll
        for (int o = 16; o > 0; o >>= 1) {
            sq += __shfl_xor_sync(0xffffffffu, sq, o);
            sk += __shfl_xor_sync(0xffffffffu, sk, o);
        }
        if (lane == 0) {
            invq[row] = rsqrtf(sq);
            s_ik[warp * 4 + rr] = rsqrtf(sk);
        }
    }
    __syncthreads();

    float ax = 0.f, ay = 0.f, az = 0.f, aw = 0.f;
    for (int r = 0; r < 32; r++) {
        int row = R0 + r;
        bool msk = maskIsByte ? (mask[row] != 0) : (mask32[row] != 0);
        if (!msk) {
            float ik = s_ik[r];
            const float4* base = (const float4*)(qkv + (size_t)row * E3_);
            float4 k4 = base[256 + tid];
            float4 v4 = base[512 + tid];
            ax += k4.x * ik * v4.x;
            ay += k4.y * ik * v4.y;
            az += k4.z * ik * v4.z;
            aw += k4.w * ik * v4.w;
        }
    }
    float* kvb = kv + b * DD_ + tid * 4;
    atomicAdd(kvb + 0, ax);
    atomicAdd(kvb + 1, ay);
    atomicAdd(kvb + 2, az);
    atomicAdd(kvb + 3, aw);
}

// A2 = q * invq[row] * kv[b,:] -> fp16. One 128-thread block per row.
__global__ __launch_bounds__(128) void stage3_kernel(
    const float* __restrict__ qkv, const float* __restrict__ invq,
    const float* __restrict__ kv, __half* __restrict__ out)
{
    int tid = threadIdx.x;
    int row = blockIdx.x;
    int b = row >> 12;
    float s = invq[row];
    const float* qp = qkv + (size_t)row * E3_ + tid * 8;
    const float* kp = kv + b * DD_ + tid * 8;
    float4 q0 = *(const float4*)(qp);
    float4 q1 = *(const float4*)(qp + 4);
    float4 k0 = *(const float4*)(kp);
    float4 k1 = *(const float4*)(kp + 4);
    union { uint4 u; __half2 h[4]; } r;
    r.h[0] = __floats2half2_rn(q0.x * s * k0.x, q0.y * s * k0.y);
    r.h[1] = __floats2half2_rn(q0.z * s * k0.z, q0.w * s * k0.w);
    r.h[2] = __floats2half2_rn(q1.x * s * k1.x, q1.y * s * k1.y);
    r.h[3] = __floats2half2_rn(q1.z * s * k1.z, q1.w * s * k1.w);
    *(uint4*)(out + (size_t)row * DD_ + tid * 8) = r.u;
}

// ---------------------------------------------------------------------------
// Launch
// ---------------------------------------------------------------------------
extern "C" void kernel_launch(void* const* d_in, const int* in_sizes, int n_in,
                              void* d_out, int out_size)
{
    const float* x = (const float*)d_in[0];
    const unsigned char* mask = (const unsigned char*)d_in[1];
    const float* Wqkv = (const float*)d_in[2];
    const float* bqkv = (const float*)d_in[3];
    const float* Wout = (const float*)d_in[4];
    const float* bout = (const float*)d_in[5];
    float* out = (float*)d_out;

    float *p_qkv, *p_invq, *p_kv;
    __half *p_xh, *p_wqh, *p_woh;
    cudaGetSymbolAddress((void**)&p_qkv, g_qkv);
    cudaGetSymbolAddress((void**)&p_invq, g_invq);
    cudaGetSymbolAddress((void**)&p_kv, g_kv);
    cudaGetSymbolAddress((void**)&p_xh, g_xh);
    cudaGetSymbolAddress((void**)&p_wqh, g_wqh);
    cudaGetSymbolAddress((void**)&p_woh, g_woh);

    cudaFuncSetAttribute(gemm_f16_kernel,
                         cudaFuncAttributeMaxDynamicSharedMemorySize, GS_TOTAL);

    // Launch order keeps GEMM1 at ncu capture slot #4 (-s 5 -c 1).
    zero_kv_kernel<<<(BB_ * DD_ + 255) / 256, 256>>>(p_kv);
    cvt_f16_kernel<<<(MM_ * DD_ / 8 + 255) / 256, 256>>>(x, p_xh, MM_ * DD_ / 8);
    cvt_f16_kernel<<<(E3_ * DD_ / 8 + 255) / 256, 256>>>(Wqkv, p_wqh, E3_ * DD_ / 8);
    // 4: GEMM1: qkv = x @ W_qkv^T + b_qkv   (16384 x 3072)
    gemm_f16_kernel<<<dim3(E3_ / 128, MM_ / 128), NTHR, GS_TOTAL>>>(
        p_xh, p_wqh, bqkv, p_qkv, E3_);
    cvt_f16_kernel<<<(DD_ * DD_ / 8 + 255) / 256, 256>>>(Wout, p_woh, DD_ * DD_ / 8);
    detect_mask_kernel<<<1, 512>>>(mask);
    stage2_kernel<<<MM_ / 32, 256>>>(p_qkv, mask, p_invq, p_kv);
    // A2 fp16 overwrites x fp16 buffer
    stage3_kernel<<<MM_, 128>>>(p_qkv, p_invq, p_kv, p_xh);
    // GEMM2: out = A2 @ W_out^T + b_out   (16384 x 1024)
    gemm_f16_kernel<<<dim3(DD_ / 128, MM_ / 128), NTHR, GS_TOTAL>>>(
        p_xh, p_woh, bout, out, DD_);
}